// round 3
// baseline (speedup 1.0000x reference)
#include <cuda_runtime.h>
#include <cstdint>

// Problem constants (fixed shapes for GCN_8967891714538)
#define N_NODES 50000
#define N_EDGES 800000
#define IN_CH   128
#define HID_CH  128
#define OUT_CH  64

#define CHUNK   1024
#define NCHUNKS ((N_NODES + CHUNK - 1) / CHUNK)   // 49

typedef unsigned long long ull;

// ---------------- scratch (static device globals; no allocation) -------------
__device__ __align__(16) float g_hs1[(size_t)N_NODES * HID_CH];  // (x @ W1) * dinv[row]
__device__ __align__(16) float g_a1 [(size_t)N_NODES * HID_CH];  // relu(agg1 + b1)
__device__ __align__(16) float g_hs2[(size_t)N_NODES * OUT_CH];  // (a1 @ W2) * dinv[row]
__device__ __align__(16) float g_w1t[IN_CH  * HID_CH];           // W1^T  [C][K]
__device__ __align__(16) float g_w2t[HID_CH * OUT_CH];           // W2^T  [C][K]
__device__ float g_dinv[N_NODES];
__device__ int   g_ecnt[N_NODES];
__device__ int   g_fill[N_NODES];
__device__ int   g_rowptr[N_NODES + 1];
__device__ int   g_esrc[N_EDGES];
__device__ int   g_csum[NCHUNKS];
__device__ int   g_is64;   // 1 if edge_index buffer is int64, 0 if int32

// ---------------- packed fp32x2 FMA ------------------------------------------
__device__ __forceinline__ ull ffma2(ull a, ull b, ull c) {
    ull d;
    asm("fma.rn.f32x2 %0, %1, %2, %3;" : "=l"(d) : "l"(a), "l"(b), "l"(c));
    return d;
}
__device__ __forceinline__ float unpack_sum(ull v) {
    float lo, hi;
    asm("mov.b64 {%0, %1}, %2;" : "=f"(lo), "=f"(hi) : "l"(v));
    return lo + hi;
}

// ---------------- edge_index dtype detection ---------------------------------
// Genuine int64 node ids are in [0, N_NODES). If the buffer is really int32,
// a long-long read packs two random ids (lo | hi<<32) >= 2^32 almost surely.
__device__ __forceinline__ int edge_at(const void* __restrict__ ei, int idx) {
    if (g_is64) return (int)((const long long*)ei)[idx];
    return ((const int*)ei)[idx];
}

// ---------------- prep: detect + init counters + transpose W1/W2 --------------
__global__ void k_prep(const void* __restrict__ ei,
                       const float* __restrict__ W1,
                       const float* __restrict__ W2) {
    int gtid = blockIdx.x * blockDim.x + threadIdx.x;
    int nthr = gridDim.x * blockDim.x;

    if (gtid == 0) {
        const long long* p = (const long long*)ei;
        int is64 = 1;
        for (int i = 0; i < 64; i++) {           // 512 bytes — safe for both layouts
            long long v = p[i];
            if (v < 0 || v >= (long long)N_NODES) { is64 = 0; break; }
        }
        g_is64 = is64;
    }
    for (int v = gtid; v < N_NODES; v += nthr) { g_ecnt[v] = 0; g_fill[v] = 0; }
    // W1t[c*K + k] = W1[k*C + c], K = IN_CH, C = HID_CH
    for (int i = gtid; i < IN_CH * HID_CH; i += nthr) {
        int c = i / IN_CH, k = i % IN_CH;
        g_w1t[i] = W1[k * HID_CH + c];
    }
    // W2t[c*K + k] = W2[k*C + c], K = HID_CH, C = OUT_CH
    for (int i = gtid; i < HID_CH * OUT_CH; i += nthr) {
        int c = i / HID_CH, k = i % HID_CH;
        g_w2t[i] = W2[k * OUT_CH + c];
    }
}

// ---------------- CSR build ---------------------------------------------------
__global__ void k_count(const void* __restrict__ ei) {
    int e = blockIdx.x * blockDim.x + threadIdx.x;
    if (e < N_EDGES) {
        int d = edge_at(ei, N_EDGES + e);
        atomicAdd(&g_ecnt[d], 1);
    }
}

__global__ void k_chunksum() {
    __shared__ int sdata[256];
    int c = blockIdx.x, t = threadIdx.x;
    int base = c * CHUNK;
    int s = 0;
    for (int i = t; i < CHUNK; i += 256) {
        int v = base + i;
        s += (v < N_NODES) ? g_ecnt[v] : 0;
    }
    sdata[t] = s;
    __syncthreads();
    for (int off = 128; off > 0; off >>= 1) {
        if (t < off) sdata[t] += sdata[t + off];
        __syncthreads();
    }
    if (t == 0) g_csum[c] = sdata[0];
}

// chunk-local scan + global offset + dinv, all in one kernel (49 blocks x 1024)
__global__ void k_scanfinal() {
    __shared__ int s[CHUNK];
    __shared__ int base;
    int c = blockIdx.x, t = threadIdx.x;
    if (t == 0) {
        int run = 0;
        for (int i = 0; i < c; i++) run += g_csum[i];
        base = run;
    }
    int v = c * CHUNK + t;
    int cnt = (v < N_NODES) ? g_ecnt[v] : 0;
    s[t] = cnt;
    __syncthreads();
    // Hillis-Steele inclusive scan
    for (int off = 1; off < CHUNK; off <<= 1) {
        int val = (t >= off) ? s[t - off] : 0;
        __syncthreads();
        s[t] += val;
        __syncthreads();
    }
    if (v < N_NODES) {
        g_rowptr[v] = base + s[t] - cnt;           // exclusive
        g_dinv[v]   = rsqrtf((float)(cnt + 1));    // +1 self-loop
    }
    if (c == NCHUNKS - 1 && t == 0) {
        int last = N_NODES - c * CHUNK - 1;        // last valid index in this chunk
        g_rowptr[N_NODES] = base + s[last];
    }
}

__global__ void k_fill(const void* __restrict__ ei) {
    int e = blockIdx.x * blockDim.x + threadIdx.x;
    if (e < N_EDGES) {
        int sN = edge_at(ei, e);
        int d  = edge_at(ei, N_EDGES + e);
        int pos = g_rowptr[d] + atomicAdd(&g_fill[d], 1);
        g_esrc[pos] = sN;
    }
}

// ---------------- GEMM (fp32x2 packed FMA) with dinv row-scale epilogue -------
// blockDim.x == C (thread owns one output column); R rows per block.
// Wt is [C][K] so (k,k+1) weight lanes are adjacent -> packed 64-bit operands.
template<int K, int C>
__device__ __forceinline__ void gemm_body(const float* __restrict__ X,
                                          const float* __restrict__ Wt,
                                          float* __restrict__ out) {
    constexpr int R = 16;
    const int t    = threadIdx.x;
    const int row0 = blockIdx.x * R;

    ull acc[R];
#pragma unroll
    for (int r = 0; r < R; r++) acc[r] = 0ull;

    const ulonglong2* wt = (const ulonglong2*)(Wt + (size_t)t * K);
    for (int k = 0; k < K; k += 4) {
        ulonglong2 w = __ldg(&wt[k >> 2]);   // w.x=(w_k,w_k+1) w.y=(w_k+2,w_k+3)
#pragma unroll
        for (int r = 0; r < R; r++) {
            ulonglong2 xv = __ldg((const ulonglong2*)(X + (size_t)(row0 + r) * K + k));
            acc[r] = ffma2(xv.x, w.x, acc[r]);
            acc[r] = ffma2(xv.y, w.y, acc[r]);
        }
    }
#pragma unroll
    for (int r = 0; r < R; r++) {
        const int row = row0 + r;   // N_NODES % R == 0, no bounds check needed
        out[(size_t)row * C + t] = unpack_sum(acc[r]) * g_dinv[row];
    }
}

__global__ void __launch_bounds__(HID_CH) k_gemm1(const float* __restrict__ X) {
    gemm_body<IN_CH, HID_CH>(X, g_w1t, g_hs1);
}
__global__ void __launch_bounds__(OUT_CH) k_gemm2() {
    gemm_body<HID_CH, OUT_CH>(g_a1, g_w2t, g_hs2);
}

// ---------------- CSR gather aggregation -------------------------------------
// out[v] = (hs[v] + sum_{s in in(v)} hs[s]) * dinv[v] + bias  [+ relu]
template<int C, bool RELU>
__device__ __forceinline__ void agg_body(const float* __restrict__ hs,
                                         const float* __restrict__ bias,
                                         float* __restrict__ out) {
    constexpr int F4 = C / 4;   // float4 lanes per node row
    int gtid = blockIdx.x * blockDim.x + threadIdx.x;
    int node = gtid / F4;
    int j    = gtid % F4;
    if (node >= N_NODES) return;

    const float4* hv = (const float4*)hs;
    float4 acc0 = __ldg(&hv[(size_t)node * F4 + j]);   // self-loop term (pre-scaled)
    float4 acc1 = make_float4(0.f, 0.f, 0.f, 0.f);

    int beg = g_rowptr[node];
    int end = g_rowptr[node + 1];
    int e = beg;
    for (; e + 2 <= end; e += 2) {
        int s0 = g_esrc[e];
        int s1 = g_esrc[e + 1];
        float4 v0 = __ldg(&hv[(size_t)s0 * F4 + j]);
        float4 v1 = __ldg(&hv[(size_t)s1 * F4 + j]);
        acc0.x += v0.x; acc0.y += v0.y; acc0.z += v0.z; acc0.w += v0.w;
        acc1.x += v1.x; acc1.y += v1.y; acc1.z += v1.z; acc1.w += v1.w;
    }
    if (e < end) {
        int s0 = g_esrc[e];
        float4 v0 = __ldg(&hv[(size_t)s0 * F4 + j]);
        acc0.x += v0.x; acc0.y += v0.y; acc0.z += v0.z; acc0.w += v0.w;
    }
    acc0.x += acc1.x; acc0.y += acc1.y; acc0.z += acc1.z; acc0.w += acc1.w;

    float dv = g_dinv[node];
    float4 b = __ldg(&((const float4*)bias)[j]);
    float4 r;
    r.x = fmaf(acc0.x, dv, b.x);
    r.y = fmaf(acc0.y, dv, b.y);
    r.z = fmaf(acc0.z, dv, b.z);
    r.w = fmaf(acc0.w, dv, b.w);
    if (RELU) {
        r.x = fmaxf(r.x, 0.0f); r.y = fmaxf(r.y, 0.0f);
        r.z = fmaxf(r.z, 0.0f); r.w = fmaxf(r.w, 0.0f);
    }
    ((float4*)out)[(size_t)node * F4 + j] = r;
}

__global__ void k_agg1(const float* __restrict__ b1) {
    agg_body<HID_CH, true>(g_hs1, b1, g_a1);
}
__global__ void k_agg2(const float* __restrict__ b2, float* __restrict__ out) {
    agg_body<OUT_CH, false>(g_hs2, b2, out);
}

// ---------------- launch ------------------------------------------------------
extern "C" void kernel_launch(void* const* d_in, const int* in_sizes, int n_in,
                              void* d_out, int out_size) {
    const float* x  = (const float*)d_in[0];
    const void*  ei = d_in[1];
    const float* W1 = (const float*)d_in[2];
    const float* b1 = (const float*)d_in[3];
    const float* W2 = (const float*)d_in[4];
    const float* b2 = (const float*)d_in[5];
    float* out = (float*)d_out;
    (void)in_sizes; (void)n_in; (void)out_size;

    const int TB = 256;

    // #1 prep: dtype detect + counter init + W transposes
    k_prep     <<<256, TB>>>(ei, W1, W2);
    // #2..#5 CSR build (+ dinv fused into the scan)
    k_count    <<<(N_EDGES + TB - 1) / TB, TB>>>(ei);
    k_chunksum <<<NCHUNKS, 256>>>();
    k_scanfinal<<<NCHUNKS, CHUNK>>>();
    k_fill     <<<(N_EDGES + TB - 1) / TB, TB>>>(ei);

    // #6 (ncu -s 5 -c 1 capture target) Layer 1 GEMM: hs1 = (x @ W1) * dinv
    k_gemm1<<<N_NODES / 16, HID_CH>>>(x);
    // #7 a1 = relu(gather(hs1)*dinv + b1)
    k_agg1<<<N_NODES * (HID_CH / 4) / TB, TB>>>(b1);

    // #8 Layer 2 GEMM: hs2 = (a1 @ W2) * dinv
    k_gemm2<<<N_NODES / 16, OUT_CH>>>();
    // #9 out = gather(hs2)*dinv + b2
    k_agg2<<<N_NODES * (OUT_CH / 4) / TB, TB>>>(b2, out);
}